// round 1
// baseline (speedup 1.0000x reference)
#include <cuda_runtime.h>
#include <math.h>

// Problem constants
#define Bb   64
#define Ss   128
#define Hh   768
#define Aa   512
#define COn  100
#define TnK  5
#define T1K  6
#define Nn   64
#define SCn  12
#define MSZ  (Bb*Ss*Hh)      // 6291456
#define M1   (Bb*Ss)         // 8192

// Scratch (static device globals — allocation-free)
__device__ float g_h1[T1K * M1 * Aa];        // [6][8192][512]
__device__ float g_h2[T1K * MSZ];            // [6][B][S][H]
__device__ float g_sq[T1K * MSZ];            // squashed capsules [j][B][S][H]
__device__ float g_aspf[Bb * 3 * COn];       // aspect_feat [B][300]
__device__ float g_asp[Bb * COn];            // fca output  [B][100]
__device__ float g_z[TnK * Bb * 3 * COn];    // gated conv feats [task][B][300]
__device__ float g_priors[Nn * Bb * T1K * SCn];
__device__ float g_vote[Nn * Bb * SCn];      // flat == [n*768 + b*12 + s]

// ---------------------------------------------------------------------------
// Tiled fp32 GEMM: C[m,n] = relu( A[m,:] . W[n,:] + bias[n] ), batched over z
// A:[M,Kd] row-major, W:[N,Kd] row-major
// ---------------------------------------------------------------------------
__global__ __launch_bounds__(256)
void gemm_relu(const float* __restrict__ A, const float* __restrict__ W,
               const float* __restrict__ bias, float* __restrict__ C,
               int M, int N, int Kd,
               long sA, long sW, long sB, long sC)
{
    int z = blockIdx.z;
    A    += z * sA;
    W    += z * sW;
    bias += z * sB;
    C    += z * sC;

    __shared__ float As[16][68];
    __shared__ float Ws[16][68];

    int t  = threadIdx.x;
    int tx = t & 15, ty = t >> 4;
    int kl = t & 15, rl = t >> 4;
    int m0 = blockIdx.y * 64, n0 = blockIdx.x * 64;

    float acc[4][4] = {};

    for (int k0 = 0; k0 < Kd; k0 += 16) {
        #pragma unroll
        for (int i = 0; i < 4; i++) {
            int r = rl + i * 16;
            As[kl][r] = A[(long)(m0 + r) * Kd + k0 + kl];
            Ws[kl][r] = W[(long)(n0 + r) * Kd + k0 + kl];
        }
        __syncthreads();
        #pragma unroll
        for (int kk = 0; kk < 16; kk++) {
            float4 a4 = *(const float4*)&As[kk][ty * 4];
            float4 b4 = *(const float4*)&Ws[kk][tx * 4];
            float av[4] = {a4.x, a4.y, a4.z, a4.w};
            float bv[4] = {b4.x, b4.y, b4.z, b4.w};
            #pragma unroll
            for (int i = 0; i < 4; i++)
                #pragma unroll
                for (int j = 0; j < 4; j++)
                    acc[i][j] += av[i] * bv[j];
        }
        __syncthreads();
    }

    #pragma unroll
    for (int i = 0; i < 4; i++) {
        int m = m0 + ty * 4 + i;
        #pragma unroll
        for (int j = 0; j < 4; j++) {
            int n = n0 + tx * 4 + j;
            float v = acc[i][j] + bias[n];
            C[(long)m * N + n] = v > 0.f ? v : 0.f;
        }
    }
}

// ---------------------------------------------------------------------------
// Squash across the 6 capsules per (b,s,h) position.
// capsule j -> task: j==0 -> 5 (current), j>=1 -> j-1
// ---------------------------------------------------------------------------
__global__ void squash_kernel()
{
    int idx = blockIdx.x * 256 + threadIdx.x;
    if (idx >= MSZ) return;
    float v[6];
    v[0] = g_h2[(long)5 * MSZ + idx];
    #pragma unroll
    for (int j = 1; j < 6; j++) v[j] = g_h2[(long)(j - 1) * MSZ + idx];
    float sq = 1e-16f;
    #pragma unroll
    for (int j = 0; j < 6; j++) sq += v[j] * v[j];
    float sc = sqrtf(sq) / (1.f + sq);
    #pragma unroll
    for (int j = 0; j < 6; j++) g_sq[(long)j * MSZ + idx] = v[j] * sc;
}

// ---------------------------------------------------------------------------
// Aspect branch conv (c3, padding K-2) -> relu -> max over length
// grid (CO, B); 128 threads over output positions
// ---------------------------------------------------------------------------
template<int K>
__global__ void aspect_conv(const float* __restrict__ w, const float* __restrict__ bias, int g)
{
    __shared__ float ws[768 * K];
    __shared__ float red[128];
    int co = blockIdx.x, b = blockIdx.y, tid = threadIdx.x;

    for (int idx = tid; idx < 768 * K; idx += 128) {
        int h = idx / K, k = idx % K;
        ws[k * 768 + h] = w[co * 768 * K + idx];
    }
    __syncthreads();

    const int pad  = K - 2;
    const int Lout = 125 + K;          // 128/129/130
    float best = -1e30f;
    for (int l = tid; l < Lout; l += 128) {
        float ae = 0.f, ao = 0.f;
        #pragma unroll
        for (int k = 0; k < K; k++) {
            int s = l + k - pad;
            if (s < 0 || s >= Ss) continue;
            const float4* vp = (const float4*)&g_sq[((long)b * Ss + s) * Hh];  // capsule 0
            const float4* wp = (const float4*)&ws[k * 768];
            for (int h = 0; h < 192; h++) {
                float4 v = vp[h], q = wp[h];
                ae += v.x * q.x + v.z * q.z;
                ao += v.y * q.y + v.w * q.w;
            }
        }
        float r = ae + ao + bias[co];
        best = fmaxf(best, fmaxf(r, 0.f));
    }
    red[tid] = best;
    __syncthreads();
    for (int s = 64; s > 0; s >>= 1) {
        if (tid < s) red[tid] = fmaxf(red[tid], red[tid + s]);
        __syncthreads();
    }
    if (tid == 0) g_aspf[b * 300 + g * COn + co] = red[0];
}

// ---------------------------------------------------------------------------
// asp = aspect_feat @ fca_w^T + fca_b
// ---------------------------------------------------------------------------
__global__ void fca_kernel(const float* __restrict__ fw, const float* __restrict__ fb)
{
    __shared__ float af[300];
    int b = blockIdx.x, tid = threadIdx.x;
    for (int i = tid; i < 300; i += 128) af[i] = g_aspf[b * 300 + i];
    __syncthreads();
    if (tid < COn) {
        float s = fb[tid];
        for (int c = 0; c < 300; c++) s += af[c] * fw[tid * 300 + c];
        g_asp[b * COn + tid] = s;
    }
}

// ---------------------------------------------------------------------------
// Gated convs: z = max_l tanh(conv1) * relu(conv2 + asp), pad 0
// grid (CO, 5*B); 128 threads over output positions
// ---------------------------------------------------------------------------
template<int K>
__global__ void gated_conv(const float* __restrict__ w1, const float* __restrict__ b1,
                           const float* __restrict__ w2, const float* __restrict__ b2, int g)
{
    __shared__ float w1s[768 * K];
    __shared__ float w2s[768 * K];
    __shared__ float red[128];
    int co = blockIdx.x, tb = blockIdx.y, tid = threadIdx.x;
    int b = tb & 63, task = tb >> 6;

    for (int idx = tid; idx < 768 * K; idx += 128) {
        int h = idx / K, k = idx % K;
        w1s[k * 768 + h] = w1[co * 768 * K + idx];
        w2s[k * 768 + h] = w2[co * 768 * K + idx];
    }
    __syncthreads();

    const int Lout = Ss - K + 1;       // 126/125/124
    float val = -1e30f;
    if (tid < Lout) {
        int l = tid;
        float a1e = 0.f, a1o = 0.f, a2e = 0.f, a2o = 0.f;
        #pragma unroll
        for (int k = 0; k < K; k++) {
            const float4* vp = (const float4*)&g_sq[(((long)(task + 1) * Bb + b) * Ss + l + k) * Hh];
            const float4* p1 = (const float4*)&w1s[k * 768];
            const float4* p2 = (const float4*)&w2s[k * 768];
            for (int h = 0; h < 192; h++) {
                float4 v = vp[h], q1 = p1[h], q2 = p2[h];
                a1e += v.x * q1.x + v.z * q1.z;
                a1o += v.y * q1.y + v.w * q1.w;
                a2e += v.x * q2.x + v.z * q2.z;
                a2o += v.y * q2.y + v.w * q2.w;
            }
        }
        float zt = tanhf(a1e + a1o + b1[co]);
        float yy = a2e + a2o + b2[co] + g_asp[b * COn + co];
        val = zt * fmaxf(yy, 0.f);
    }
    red[tid] = val;
    __syncthreads();
    for (int s = 64; s > 0; s >>= 1) {
        if (tid < s) red[tid] = fmaxf(red[tid], red[tid + s]);
        __syncthreads();
    }
    if (tid == 0) g_z[tb * 300 + g * COn + co] = red[0];
}

// ---------------------------------------------------------------------------
// priors[n,b,i,s] = sum_c caps2[b,i,c] * route_w[n,i,c,s]
// caps2[b,0,:] = aspect_feat[b], caps2[b,i,:] = z[i-1][b]
// grid (B, N), 72 threads = (i,s)
// ---------------------------------------------------------------------------
__global__ void priors_kernel(const float* __restrict__ rw)
{
    __shared__ float cap[1800];
    int b = blockIdx.x, n = blockIdx.y, tid = threadIdx.x;
    for (int idx = tid; idx < 1800; idx += 72) {
        int i = idx / 300, c = idx % 300;
        cap[idx] = (i == 0) ? g_aspf[b * 300 + c] : g_z[((i - 1) * Bb + b) * 300 + c];
    }
    __syncthreads();
    int i = tid / 12, s = tid % 12;
    float acc = 0.f;
    const float* rp = rw + ((long)(n * 6 + i) * 300) * 12 + s;
    const float* cp = &cap[i * 300];
    for (int c = 0; c < 300; c++) acc += cp[c] * rp[c * 12];
    g_priors[((n * Bb + b) * 6 + i) * 12 + s] = acc;
}

// ---------------------------------------------------------------------------
// 3-iteration dynamic routing; one thread per (n,b) pair
// ---------------------------------------------------------------------------
__global__ void routing_kernel()
{
    int gid = blockIdx.x * blockDim.x + threadIdx.x;
    if (gid >= Nn * Bb) return;
    float pr[72];
    #pragma unroll
    for (int j = 0; j < 72; j++) pr[j] = g_priors[gid * 72 + j];

    float logits[6] = {0, 0, 0, 0, 0, 0};
    float vote[12];
    #pragma unroll
    for (int it = 0; it < 3; it++) {
        float mx = logits[0];
        #pragma unroll
        for (int i = 1; i < 6; i++) mx = fmaxf(mx, logits[i]);
        float e[6], se = 0.f;
        #pragma unroll
        for (int i = 0; i < 6; i++) { e[i] = expf(logits[i] - mx); se += e[i]; }
        float inv = 1.f / se;
        #pragma unroll
        for (int s = 0; s < 12; s++) {
            float v = 0.f;
            #pragma unroll
            for (int i = 0; i < 6; i++) v += e[i] * pr[i * 12 + s];
            vote[s] = v * inv;
        }
        if (it < 2) {
            float sq = 1e-16f;
            #pragma unroll
            for (int s = 0; s < 12; s++) sq += vote[s] * vote[s];
            float sc = sqrtf(sq) / (1.f + sq);
            #pragma unroll
            for (int i = 0; i < 6; i++) {
                float d = 0.f;
                #pragma unroll
                for (int s = 0; s < 12; s++) d += pr[i * 12 + s] * vote[s];
                logits[i] += d * sc;
            }
        }
    }
    #pragma unroll
    for (int s = 0; s < 12; s++) g_vote[gid * 12 + s] = vote[s];
}

// ---------------------------------------------------------------------------
// out = x + h_cur + vote.reshape(B,1,H) broadcast over S
// vote flat index: [b_out*768 + h]
// ---------------------------------------------------------------------------
__global__ void final_kernel(const float* __restrict__ x, float* __restrict__ out)
{
    int idx = blockIdx.x * 256 + threadIdx.x;
    if (idx >= MSZ) return;
    int b = idx / (Ss * Hh);
    int h = idx % Hh;
    out[idx] = x[idx] + g_h2[(long)5 * MSZ + idx] + g_vote[b * Hh + h];
}

// ---------------------------------------------------------------------------
extern "C" void kernel_launch(void* const* d_in, const int* in_sizes, int n_in,
                              void* d_out, int out_size)
{
    const float* x     = (const float*)d_in[0];
    const float* fc1_w = (const float*)d_in[1];
    const float* fc1_b = (const float*)d_in[2];
    const float* fc2_w = (const float*)d_in[3];
    const float* fc2_b = (const float*)d_in[4];
    const float* c1_w3 = (const float*)d_in[5];
    const float* c1_b3 = (const float*)d_in[6];
    const float* c1_w4 = (const float*)d_in[7];
    const float* c1_b4 = (const float*)d_in[8];
    const float* c1_w5 = (const float*)d_in[9];
    const float* c1_b5 = (const float*)d_in[10];
    const float* c2_w3 = (const float*)d_in[11];
    const float* c2_b3 = (const float*)d_in[12];
    const float* c2_w4 = (const float*)d_in[13];
    const float* c2_b4 = (const float*)d_in[14];
    const float* c2_w5 = (const float*)d_in[15];
    const float* c2_b5 = (const float*)d_in[16];
    const float* c3_w3 = (const float*)d_in[17];
    const float* c3_b3 = (const float*)d_in[18];
    const float* c3_w4 = (const float*)d_in[19];
    const float* c3_b4 = (const float*)d_in[20];
    const float* c3_w5 = (const float*)d_in[21];
    const float* c3_b5 = (const float*)d_in[22];
    const float* fca_w = (const float*)d_in[23];
    const float* fca_b = (const float*)d_in[24];
    const float* rw    = (const float*)d_in[25];
    float* out = (float*)d_out;

    float *p_h1, *p_h2;
    cudaGetSymbolAddress((void**)&p_h1, g_h1);
    cudaGetSymbolAddress((void**)&p_h2, g_h2);

    // 1) h1 = relu(x @ fc1_w^T + fc1_b)   (6 tasks, shared A)
    gemm_relu<<<dim3(Aa / 64, M1 / 64, T1K), 256>>>(
        x, fc1_w, fc1_b, p_h1, M1, Aa, Hh,
        0L, (long)Aa * Hh, (long)Aa, (long)M1 * Aa);

    // 2) h2 = relu(h1 @ fc2_w^T + fc2_b)
    gemm_relu<<<dim3(Hh / 64, M1 / 64, T1K), 256>>>(
        p_h1, fc2_w, fc2_b, p_h2, M1, Hh, Aa,
        (long)M1 * Aa, (long)Hh * Aa, (long)Hh, (long)M1 * Hh);

    // 3) squash across capsules
    squash_kernel<<<(MSZ + 255) / 256, 256>>>();

    // 4) aspect convs (c3, K=3/4/5)
    aspect_conv<3><<<dim3(COn, Bb), 128>>>(c3_w3, c3_b3, 0);
    aspect_conv<4><<<dim3(COn, Bb), 128>>>(c3_w4, c3_b4, 1);
    aspect_conv<5><<<dim3(COn, Bb), 128>>>(c3_w5, c3_b5, 2);

    // 5) fca
    fca_kernel<<<Bb, 128>>>(fca_w, fca_b);

    // 6) gated convs (c1/c2, K=3/4/5) over 5*B items
    gated_conv<3><<<dim3(COn, TnK * Bb), 128>>>(c1_w3, c1_b3, c2_w3, c2_b3, 0);
    gated_conv<4><<<dim3(COn, TnK * Bb), 128>>>(c1_w4, c1_b4, c2_w4, c2_b4, 1);
    gated_conv<5><<<dim3(COn, TnK * Bb), 128>>>(c1_w5, c1_b5, c2_w5, c2_b5, 2);

    // 7) priors
    priors_kernel<<<dim3(Bb, Nn), 72>>>(rw);

    // 8) dynamic routing
    routing_kernel<<<16, 256>>>();

    // 9) residual add
    final_kernel<<<(MSZ + 255) / 256, 256>>>(x, out);
}

// round 2
// speedup vs baseline: 11.4976x; 11.4976x over previous
#include <cuda_runtime.h>
#include <math.h>

// Problem constants
#define Bb   64
#define Ss   128
#define Hh   768
#define Aa   512
#define COn  100
#define TnK  5
#define T1K  6
#define Nn   64
#define SCn  12
#define MSZ  (Bb*Ss*Hh)      // 6291456
#define M1   (Bb*Ss)         // 8192

#define NG_PAD 2432          // 2400 gated channels padded to 19*128
#define NA_PAD 1280          // 1200 aspect channels padded to 10*128
#define MG     (TnK*M1)      // 40960 rows for gated GEMM

// Scratch (static device globals — allocation-free)
__device__ float g_h1[T1K * M1 * Aa];          // [6][8192][512]
__device__ float g_h2[T1K * MSZ];              // [6][B][S][H]
__device__ float g_sq[T1K * MSZ];              // squashed capsules [j][B][S][H]
__device__ float g_Wg[NG_PAD * Hh];            // packed gated conv weights [ch][768]
__device__ float g_Wa[NA_PAD * Hh];            // packed aspect conv weights
__device__ float g_Yg[(long)MG * NG_PAD];      // gated conv GEMM output
__device__ float g_Ya[(long)M1 * NA_PAD];      // aspect conv GEMM output
__device__ float g_aspf[Bb * 3 * COn];         // aspect_feat [B][300]
__device__ float g_asp[Bb * COn];              // fca output  [B][100]
__device__ float g_z[TnK * Bb * 3 * COn];      // gated conv feats [task][B][300]
__device__ float g_priors[Nn * Bb * T1K * SCn];
__device__ float g_vote[Nn * Bb * SCn];        // flat == [n*768 + b*12 + s]

// ---------------------------------------------------------------------------
// 128x128x8 tiled fp32 GEMM: C[m,n] = (relu)( A[m,:] . W[n,:] + bias[n] )
// A:[M,Kd] row-major, W:[N,Kd] row-major. Batched over z via strides.
// 256 threads, 8x8 microtile, smem stride 132 (conflict-free transpose store),
// register prefetch of next k-tile. All dims must be multiples of tile sizes.
// ---------------------------------------------------------------------------
template<bool RELU, bool HASB>
__global__ __launch_bounds__(256)
void gemm128(const float* __restrict__ A, const float* __restrict__ W,
             const float* __restrict__ bias, float* __restrict__ C,
             int N, int Kd, long sA, long sW, long sB, long sC)
{
    A += blockIdx.z * sA;
    W += blockIdx.z * sW;
    C += blockIdx.z * sC;
    if (HASB) bias += blockIdx.z * sB;

    __shared__ float As[8 * 132];
    __shared__ float Ws[8 * 132];

    int tid = threadIdx.x;
    int tx = tid & 15, ty = tid >> 4;
    int m0 = blockIdx.y * 128, n0 = blockIdx.x * 128;

    int lr = tid >> 1;           // 0..127
    int lk = (tid & 1) * 4;      // 0 or 4

    const float* Ag = A + (long)(m0 + lr) * Kd + lk;
    const float* Wgp = W + (long)(n0 + lr) * Kd + lk;

    float4 a_pf = *(const float4*)Ag;
    float4 w_pf = *(const float4*)Wgp;

    float acc[8][8] = {};

    for (int k0 = 0; k0 < Kd; k0 += 8) {
        As[(lk + 0) * 132 + lr] = a_pf.x;
        As[(lk + 1) * 132 + lr] = a_pf.y;
        As[(lk + 2) * 132 + lr] = a_pf.z;
        As[(lk + 3) * 132 + lr] = a_pf.w;
        Ws[(lk + 0) * 132 + lr] = w_pf.x;
        Ws[(lk + 1) * 132 + lr] = w_pf.y;
        Ws[(lk + 2) * 132 + lr] = w_pf.z;
        Ws[(lk + 3) * 132 + lr] = w_pf.w;
        __syncthreads();

        if (k0 + 8 < Kd) {
            a_pf = *(const float4*)(Ag + k0 + 8);
            w_pf = *(const float4*)(Wgp + k0 + 8);
        }

        #pragma unroll
        for (int kk = 0; kk < 8; kk++) {
            float4 a0 = *(const float4*)&As[kk * 132 + ty * 8];
            float4 a1 = *(const float4*)&As[kk * 132 + ty * 8 + 4];
            float4 w0 = *(const float4*)&Ws[kk * 132 + tx * 8];
            float4 w1 = *(const float4*)&Ws[kk * 132 + tx * 8 + 4];
            float av[8] = {a0.x, a0.y, a0.z, a0.w, a1.x, a1.y, a1.z, a1.w};
            float wv[8] = {w0.x, w0.y, w0.z, w0.w, w1.x, w1.y, w1.z, w1.w};
            #pragma unroll
            for (int i = 0; i < 8; i++)
                #pragma unroll
                for (int j = 0; j < 8; j++)
                    acc[i][j] += av[i] * wv[j];
        }
        __syncthreads();
    }

    float bj[8];
    #pragma unroll
    for (int j = 0; j < 8; j++)
        bj[j] = HASB ? bias[n0 + tx * 8 + j] : 0.f;

    #pragma unroll
    for (int i = 0; i < 8; i++) {
        long m = m0 + ty * 8 + i;
        float* Cp = C + m * (long)N + n0 + tx * 8;
        #pragma unroll
        for (int j = 0; j < 8; j += 4) {
            float4 v;
            v.x = acc[i][j + 0] + bj[j + 0];
            v.y = acc[i][j + 1] + bj[j + 1];
            v.z = acc[i][j + 2] + bj[j + 2];
            v.w = acc[i][j + 3] + bj[j + 3];
            if (RELU) {
                v.x = fmaxf(v.x, 0.f); v.y = fmaxf(v.y, 0.f);
                v.z = fmaxf(v.z, 0.f); v.w = fmaxf(v.w, 0.f);
            }
            *(float4*)(Cp + j) = v;
        }
    }
}

// ---------------------------------------------------------------------------
// Weight packing: Wg[ch][h], ch = kg*200 + conv*100 + co, kg=(K,k) pair
// kg<3: K=3 k=kg; kg<7: K=4 k=kg-3; else K=5 k=kg-7. src w[co*768*K + h*K + k]
// ---------------------------------------------------------------------------
__device__ __forceinline__ void decode_kg(int kg, int& K, int& k)
{
    if (kg < 3)      { K = 3; k = kg; }
    else if (kg < 7) { K = 4; k = kg - 3; }
    else             { K = 5; k = kg - 7; }
}

__global__ void pack_wg(const float* __restrict__ c1w3, const float* __restrict__ c1w4,
                        const float* __restrict__ c1w5, const float* __restrict__ c2w3,
                        const float* __restrict__ c2w4, const float* __restrict__ c2w5)
{
    long idx = (long)blockIdx.x * 256 + threadIdx.x;
    if (idx >= (long)NG_PAD * Hh) return;
    int ch = idx / Hh, h = idx % Hh;
    float v = 0.f;
    if (ch < 2400) {
        int kg = ch / 200, r = ch % 200;
        int conv = r / 100, co = r % 100;
        int K, k; decode_kg(kg, K, k);
        const float* w;
        if (conv == 0) w = (K == 3) ? c1w3 : (K == 4) ? c1w4 : c1w5;
        else           w = (K == 3) ? c2w3 : (K == 4) ? c2w4 : c2w5;
        v = w[(long)co * Hh * K + h * K + k];
    }
    g_Wg[idx] = v;
}

__global__ void pack_wa(const float* __restrict__ c3w3, const float* __restrict__ c3w4,
                        const float* __restrict__ c3w5)
{
    long idx = (long)blockIdx.x * 256 + threadIdx.x;
    if (idx >= (long)NA_PAD * Hh) return;
    int ch = idx / Hh, h = idx % Hh;
    float v = 0.f;
    if (ch < 1200) {
        int kg = ch / 100, co = ch % 100;
        int K, k; decode_kg(kg, K, k);
        const float* w = (K == 3) ? c3w3 : (K == 4) ? c3w4 : c3w5;
        v = w[(long)co * Hh * K + h * K + k];
    }
    g_Wa[idx] = v;
}

// ---------------------------------------------------------------------------
// Squash across the 6 capsules per (b,s,h) position.
// ---------------------------------------------------------------------------
__global__ void squash_kernel()
{
    int idx = blockIdx.x * 256 + threadIdx.x;
    if (idx >= MSZ) return;
    float v[6];
    v[0] = g_h2[(long)5 * MSZ + idx];
    #pragma unroll
    for (int j = 1; j < 6; j++) v[j] = g_h2[(long)(j - 1) * MSZ + idx];
    float sq = 1e-16f;
    #pragma unroll
    for (int j = 0; j < 6; j++) sq += v[j] * v[j];
    float sc = sqrtf(sq) / (1.f + sq);
    #pragma unroll
    for (int j = 0; j < 6; j++) g_sq[(long)j * MSZ + idx] = v[j] * sc;
}

// ---------------------------------------------------------------------------
// Aspect epilogue: combine shifted GEMM columns, relu, max over positions.
// grid(B), 320 threads; t = g*100+co
// ---------------------------------------------------------------------------
__global__ void aspect_epi(const float* __restrict__ b3, const float* __restrict__ b4,
                           const float* __restrict__ b5)
{
    int b = blockIdx.x, t = threadIdx.x;
    if (t >= 300) return;
    int g = t / 100, co = t % 100;
    int K = 3 + g;
    int base = (g == 0) ? 0 : (g == 1) ? 3 : 7;
    int pad = K - 2;
    const float* bias = (g == 0) ? b3 : (g == 1) ? b4 : b5;
    float bb = bias[co];
    int Lout = 125 + K;
    float best = 0.f;            // relu output >= 0
    for (int l = 0; l < Lout; l++) {
        float s = bb;
        for (int k = 0; k < K; k++) {
            int ss = l + k - pad;
            if (ss >= 0 && ss < Ss)
                s += g_Ya[((long)b * Ss + ss) * NA_PAD + (base + k) * 100 + co];
        }
        best = fmaxf(best, s);
    }
    g_aspf[b * 300 + t] = best;
}

// ---------------------------------------------------------------------------
// asp = aspect_feat @ fca_w^T + fca_b
// ---------------------------------------------------------------------------
__global__ void fca_kernel(const float* __restrict__ fw, const float* __restrict__ fb)
{
    __shared__ float af[300];
    int b = blockIdx.x, tid = threadIdx.x;
    for (int i = tid; i < 300; i += 128) af[i] = g_aspf[b * 300 + i];
    __syncthreads();
    if (tid < COn) {
        float s = fb[tid];
        for (int c = 0; c < 300; c++) s += af[c] * fw[tid * 300 + c];
        g_asp[b * COn + tid] = s;
    }
}

// ---------------------------------------------------------------------------
// Gated epilogue: z = max_l tanh(conv1) * relu(conv2 + asp)
// grid(5*B), 320 threads
// ---------------------------------------------------------------------------
__global__ void gated_epi(const float* __restrict__ b13, const float* __restrict__ b14,
                          const float* __restrict__ b15, const float* __restrict__ b23,
                          const float* __restrict__ b24, const float* __restrict__ b25)
{
    int i = blockIdx.x, t = threadIdx.x;
    if (t >= 300) return;
    int b = i & 63;
    int g = t / 100, co = t % 100;
    int K = 3 + g;
    int base = (g == 0) ? 0 : (g == 1) ? 3 : 7;
    const float* bias1 = (g == 0) ? b13 : (g == 1) ? b14 : b15;
    const float* bias2 = (g == 0) ? b23 : (g == 1) ? b24 : b25;
    float c1b = bias1[co];
    float c2b = bias2[co] + g_asp[b * COn + co];
    int Lout = Ss - K + 1;
    float best = -1e30f;
    for (int l = 0; l < Lout; l++) {
        float s1 = c1b, s2 = c2b;
        for (int k = 0; k < K; k++) {
            long row = (long)i * Ss + l + k;
            s1 += g_Yg[row * NG_PAD + (base + k) * 200 + co];
            s2 += g_Yg[row * NG_PAD + (base + k) * 200 + 100 + co];
        }
        float val = tanhf(s1) * fmaxf(s2, 0.f);
        best = fmaxf(best, val);
    }
    g_z[i * 300 + t] = best;
}

// ---------------------------------------------------------------------------
// priors[n,b,i,s] = sum_c caps2[b,i,c] * route_w[n,i,c,s]
// ---------------------------------------------------------------------------
__global__ void priors_kernel(const float* __restrict__ rw)
{
    __shared__ float cap[1800];
    int b = blockIdx.x, n = blockIdx.y, tid = threadIdx.x;
    for (int idx = tid; idx < 1800; idx += 72) {
        int i = idx / 300, c = idx % 300;
        cap[idx] = (i == 0) ? g_aspf[b * 300 + c] : g_z[((i - 1) * Bb + b) * 300 + c];
    }
    __syncthreads();
    int i = tid / 12, s = tid % 12;
    float acc = 0.f;
    const float* rp = rw + ((long)(n * 6 + i) * 300) * 12 + s;
    const float* cp = &cap[i * 300];
    for (int c = 0; c < 300; c++) acc += cp[c] * rp[c * 12];
    g_priors[((n * Bb + b) * 6 + i) * 12 + s] = acc;
}

// ---------------------------------------------------------------------------
// 3-iteration dynamic routing; one thread per (n,b) pair
// ---------------------------------------------------------------------------
__global__ void routing_kernel()
{
    int gid = blockIdx.x * blockDim.x + threadIdx.x;
    if (gid >= Nn * Bb) return;
    float pr[72];
    #pragma unroll
    for (int j = 0; j < 72; j++) pr[j] = g_priors[gid * 72 + j];

    float logits[6] = {0, 0, 0, 0, 0, 0};
    float vote[12];
    #pragma unroll
    for (int it = 0; it < 3; it++) {
        float mx = logits[0];
        #pragma unroll
        for (int i = 1; i < 6; i++) mx = fmaxf(mx, logits[i]);
        float e[6], se = 0.f;
        #pragma unroll
        for (int i = 0; i < 6; i++) { e[i] = expf(logits[i] - mx); se += e[i]; }
        float inv = 1.f / se;
        #pragma unroll
        for (int s = 0; s < 12; s++) {
            float v = 0.f;
            #pragma unroll
            for (int i = 0; i < 6; i++) v += e[i] * pr[i * 12 + s];
            vote[s] = v * inv;
        }
        if (it < 2) {
            float sq = 1e-16f;
            #pragma unroll
            for (int s = 0; s < 12; s++) sq += vote[s] * vote[s];
            float sc = sqrtf(sq) / (1.f + sq);
            #pragma unroll
            for (int i = 0; i < 6; i++) {
                float d = 0.f;
                #pragma unroll
                for (int s = 0; s < 12; s++) d += pr[i * 12 + s] * vote[s];
                logits[i] += d * sc;
            }
        }
    }
    #pragma unroll
    for (int s = 0; s < 12; s++) g_vote[gid * 12 + s] = vote[s];
}

// ---------------------------------------------------------------------------
// out = x + h_cur + vote.reshape(B,1,H) broadcast over S
// ---------------------------------------------------------------------------
__global__ void final_kernel(const float* __restrict__ x, float* __restrict__ out)
{
    int idx = blockIdx.x * 256 + threadIdx.x;
    if (idx >= MSZ) return;
    int b = idx / (Ss * Hh);
    int h = idx % Hh;
    out[idx] = x[idx] + g_h2[(long)5 * MSZ + idx] + g_vote[b * Hh + h];
}

// ---------------------------------------------------------------------------
extern "C" void kernel_launch(void* const* d_in, const int* in_sizes, int n_in,
                              void* d_out, int out_size)
{
    const float* x     = (const float*)d_in[0];
    const float* fc1_w = (const float*)d_in[1];
    const float* fc1_b = (const float*)d_in[2];
    const float* fc2_w = (const float*)d_in[3];
    const float* fc2_b = (const float*)d_in[4];
    const float* c1_w3 = (const float*)d_in[5];
    const float* c1_b3 = (const float*)d_in[6];
    const float* c1_w4 = (const float*)d_in[7];
    const float* c1_b4 = (const float*)d_in[8];
    const float* c1_w5 = (const float*)d_in[9];
    const float* c1_b5 = (const float*)d_in[10];
    const float* c2_w3 = (const float*)d_in[11];
    const float* c2_b3 = (const float*)d_in[12];
    const float* c2_w4 = (const float*)d_in[13];
    const float* c2_b4 = (const float*)d_in[14];
    const float* c2_w5 = (const float*)d_in[15];
    const float* c2_b5 = (const float*)d_in[16];
    const float* c3_w3 = (const float*)d_in[17];
    const float* c3_b3 = (const float*)d_in[18];
    const float* c3_w4 = (const float*)d_in[19];
    const float* c3_b4 = (const float*)d_in[20];
    const float* c3_w5 = (const float*)d_in[21];
    const float* c3_b5 = (const float*)d_in[22];
    const float* fca_w = (const float*)d_in[23];
    const float* fca_b = (const float*)d_in[24];
    const float* rw    = (const float*)d_in[25];
    float* out = (float*)d_out;

    float *p_h1, *p_h2, *p_sq, *p_Wg, *p_Wa, *p_Yg, *p_Ya;
    cudaGetSymbolAddress((void**)&p_h1, g_h1);
    cudaGetSymbolAddress((void**)&p_h2, g_h2);
    cudaGetSymbolAddress((void**)&p_sq, g_sq);
    cudaGetSymbolAddress((void**)&p_Wg, g_Wg);
    cudaGetSymbolAddress((void**)&p_Wa, g_Wa);
    cudaGetSymbolAddress((void**)&p_Yg, g_Yg);
    cudaGetSymbolAddress((void**)&p_Ya, g_Ya);

    // 0) pack conv weights (independent of data path)
    pack_wg<<<((long)NG_PAD * Hh + 255) / 256, 256>>>(c1_w3, c1_w4, c1_w5, c2_w3, c2_w4, c2_w5);
    pack_wa<<<((long)NA_PAD * Hh + 255) / 256, 256>>>(c3_w3, c3_w4, c3_w5);

    // 1) h1 = relu(x @ fc1_w^T + fc1_b)   (6 tasks, shared A)
    gemm128<true, true><<<dim3(Aa / 128, M1 / 128, T1K), 256>>>(
        x, fc1_w, fc1_b, p_h1, Aa, Hh,
        0L, (long)Aa * Hh, (long)Aa, (long)M1 * Aa);

    // 2) h2 = relu(h1 @ fc2_w^T + fc2_b)
    gemm128<true, true><<<dim3(Hh / 128, M1 / 128, T1K), 256>>>(
        p_h1, fc2_w, fc2_b, p_h2, Hh, Aa,
        (long)M1 * Aa, (long)Hh * Aa, (long)Hh, (long)M1 * Hh);

    // 3) squash across capsules
    squash_kernel<<<(MSZ + 255) / 256, 256>>>();

    // 4) conv GEMMs (aspect: capsule 0; gated: capsules 1..5)
    gemm128<false, false><<<dim3(NA_PAD / 128, M1 / 128, 1), 256>>>(
        p_sq, p_Wa, nullptr, p_Ya, NA_PAD, Hh, 0L, 0L, 0L, 0L);
    gemm128<false, false><<<dim3(NG_PAD / 128, MG / 128, 1), 256>>>(
        p_sq + (long)MSZ, p_Wg, nullptr, p_Yg, NG_PAD, Hh, 0L, 0L, 0L, 0L);

    // 5) aspect epilogue -> fca -> gated epilogue
    aspect_epi<<<Bb, 320>>>(c3_b3, c3_b4, c3_b5);
    fca_kernel<<<Bb, 128>>>(fca_w, fca_b);
    gated_epi<<<TnK * Bb, 320>>>(c1_b3, c1_b4, c1_b5, c2_b3, c2_b4, c2_b5);

    // 6) priors + routing
    priors_kernel<<<dim3(Bb, Nn), 72>>>(rw);
    routing_kernel<<<16, 256>>>();

    // 7) residual add
    final_kernel<<<(MSZ + 255) / 256, 256>>>(x, out);
}

// round 4
// speedup vs baseline: 24.4301x; 2.1248x over previous
#include <cuda_runtime.h>
#include <cuda_bf16.h>
#include <math.h>
#include <stdint.h>

// Problem constants
#define Bb   64
#define Ss   128
#define Hh   768
#define Aa   512
#define COn  100
#define TnK  5
#define T1K  6
#define Nn   64
#define SCn  12
#define MSZ  (Bb*Ss*Hh)      // 6291456
#define M1   (Bb*Ss)         // 8192

#define NG_PAD 2432          // 2400 gated channels padded to 19*128
#define NA_PAD 1280          // 1200 aspect channels padded to 10*128
#define MG     (TnK*M1)      // 40960 rows for gated GEMM

// Scratch (static device globals — allocation-free)
__device__ float g_h1[T1K * M1 * Aa];
__device__ float g_h2[T1K * MSZ];
__device__ float g_sq[T1K * MSZ];
__device__ float g_Wg[NG_PAD * Hh];
__device__ float g_Wa[NA_PAD * Hh];
__device__ float g_Yg[(long)MG * NG_PAD];
__device__ float g_Ya[(long)M1 * NA_PAD];
__device__ float g_aspf[Bb * 3 * COn];
__device__ float g_asp[Bb * COn];
__device__ float g_z[TnK * Bb * 3 * COn];
__device__ float g_priors[Nn * Bb * T1K * SCn];
__device__ float g_vote[Nn * Bb * SCn];

// ===========================================================================
// Portable warp-level bf16 MMA (HMMA), fp32 accumulate
// ===========================================================================
__device__ __forceinline__ void mma16816(float* c, const uint32_t* a, const uint32_t* b)
{
    asm volatile(
        "mma.sync.aligned.m16n8k16.row.col.f32.bf16.bf16.f32 "
        "{%0,%1,%2,%3}, {%4,%5,%6,%7}, {%8,%9}, {%0,%1,%2,%3};"
        : "+f"(c[0]), "+f"(c[1]), "+f"(c[2]), "+f"(c[3])
        : "r"(a[0]), "r"(a[1]), "r"(a[2]), "r"(a[3]), "r"(b[0]), "r"(b[1]));
}

// fp32x8 -> packed bf16x2 hi[4] + lo[4] (Dekker split)
__device__ __forceinline__ void split8(float4 f0, float4 f1, uint32_t* h, uint32_t* l)
{
    float f[8] = {f0.x, f0.y, f0.z, f0.w, f1.x, f1.y, f1.z, f1.w};
    #pragma unroll
    for (int i = 0; i < 4; i++) {
        uint32_t hp;
        asm("cvt.rn.bf16x2.f32 %0, %1, %2;" : "=r"(hp) : "f"(f[2*i+1]), "f"(f[2*i]));
        float h0 = __uint_as_float(hp << 16);
        float h1 = __uint_as_float(hp & 0xffff0000u);
        float r0 = f[2*i]     - h0;
        float r1 = f[2*i + 1] - h1;
        uint32_t lp;
        asm("cvt.rn.bf16x2.f32 %0, %1, %2;" : "=r"(lp) : "f"(r1), "f"(r0));
        h[i] = hp; l[i] = lp;
    }
}

// ===========================================================================
// Warp-MMA GEMM: C[m,n] = (relu)(sum_k A[m,k]*W[n,k] + bias[n]), z-batched
// 128x128 tile, 8 warps (2x4), K-chunks of 32, split-bf16 (3 MMAs/frag),
// double-buffered smem, single barrier per chunk, register prefetch.
// ===========================================================================
#define KC       32
#define ASTR     40                    // bf16 elems per smem row (conflict-free)
#define TILE_ELE (128 * ASTR)          // 5120 elems
#define STAGE_ELE (4 * TILE_ELE)       // Ahi, Alo, Bhi, Blo
#define SMEM_REQ (2 * STAGE_ELE * 2)   // bytes = 81920

template<bool RELU, bool HASB>
__global__ __launch_bounds__(256)
void mma_gemm(const float* __restrict__ A, const float* __restrict__ W,
              const float* __restrict__ bias, float* __restrict__ C,
              int N, int Kd, long sA, long sW, long sB, long sC)
{
    extern __shared__ __nv_bfloat16 sm[];
    A += blockIdx.z * sA;
    W += blockIdx.z * sW;
    C += blockIdx.z * sC;
    if (HASB) bias += blockIdx.z * sB;
    int m0 = blockIdx.y * 128, n0 = blockIdx.x * 128;

    int tid = threadIdx.x, lane = tid & 31, wid = tid >> 5;
    int wm = wid >> 2, wn = wid & 3;       // warp tile: rows wm*64, cols wn*32
    int gid = lane >> 2, tig = lane & 3;

    // per-thread global load coords: 8 consecutive floats, 2 row groups
    int row0 = tid >> 2;                   // 0..63
    int cc8  = (tid & 3) * 8;              // 0/8/16/24

    const float* Ap0 = A + (long)(m0 + row0) * Kd + cc8;
    const float* Ap1 = A + (long)(m0 + row0 + 64) * Kd + cc8;
    const float* Wp0 = W + (long)(n0 + row0) * Kd + cc8;
    const float* Wp1 = W + (long)(n0 + row0 + 64) * Kd + cc8;

    // prefetch chunk 0
    float4 fa0 = *(const float4*)(Ap0),     fa1 = *(const float4*)(Ap0 + 4);
    float4 fa2 = *(const float4*)(Ap1),     fa3 = *(const float4*)(Ap1 + 4);
    float4 fb0 = *(const float4*)(Wp0),     fb1 = *(const float4*)(Wp0 + 4);
    float4 fb2 = *(const float4*)(Wp1),     fb3 = *(const float4*)(Wp1 + 4);

    float acc[4][4][4] = {};
    int nch = Kd / KC;

    for (int c = 0; c < nch; c++) {
        __nv_bfloat16* Ah = sm + (c & 1) * STAGE_ELE;
        __nv_bfloat16* Al = Ah + TILE_ELE;
        __nv_bfloat16* Bh = Al + TILE_ELE;
        __nv_bfloat16* Bl = Bh + TILE_ELE;

        // convert & store current chunk
        {
            uint32_t h[4], l[4];
            split8(fa0, fa1, h, l);
            *(uint4*)(Ah + row0 * ASTR + cc8) = make_uint4(h[0], h[1], h[2], h[3]);
            *(uint4*)(Al + row0 * ASTR + cc8) = make_uint4(l[0], l[1], l[2], l[3]);
            split8(fa2, fa3, h, l);
            *(uint4*)(Ah + (row0 + 64) * ASTR + cc8) = make_uint4(h[0], h[1], h[2], h[3]);
            *(uint4*)(Al + (row0 + 64) * ASTR + cc8) = make_uint4(l[0], l[1], l[2], l[3]);
            split8(fb0, fb1, h, l);
            *(uint4*)(Bh + row0 * ASTR + cc8) = make_uint4(h[0], h[1], h[2], h[3]);
            *(uint4*)(Bl + row0 * ASTR + cc8) = make_uint4(l[0], l[1], l[2], l[3]);
            split8(fb2, fb3, h, l);
            *(uint4*)(Bh + (row0 + 64) * ASTR + cc8) = make_uint4(h[0], h[1], h[2], h[3]);
            *(uint4*)(Bl + (row0 + 64) * ASTR + cc8) = make_uint4(l[0], l[1], l[2], l[3]);
        }

        // prefetch next chunk
        if (c + 1 < nch) {
            int k1 = (c + 1) * KC;
            fa0 = *(const float4*)(Ap0 + k1); fa1 = *(const float4*)(Ap0 + k1 + 4);
            fa2 = *(const float4*)(Ap1 + k1); fa3 = *(const float4*)(Ap1 + k1 + 4);
            fb0 = *(const float4*)(Wp0 + k1); fb1 = *(const float4*)(Wp0 + k1 + 4);
            fb2 = *(const float4*)(Wp1 + k1); fb3 = *(const float4*)(Wp1 + k1 + 4);
        }

        __syncthreads();

        #pragma unroll
        for (int kk = 0; kk < KC; kk += 16) {
            uint32_t bh[4][2], bl[4][2];
            #pragma unroll
            for (int nt = 0; nt < 4; nt++) {
                int off = (wn * 32 + nt * 8 + gid) * ASTR + kk + tig * 2;
                bh[nt][0] = *(const uint32_t*)(Bh + off);
                bh[nt][1] = *(const uint32_t*)(Bh + off + 8);
                bl[nt][0] = *(const uint32_t*)(Bl + off);
                bl[nt][1] = *(const uint32_t*)(Bl + off + 8);
            }
            #pragma unroll
            for (int mt = 0; mt < 4; mt++) {
                int off = (wm * 64 + mt * 16 + gid) * ASTR + kk + tig * 2;
                uint32_t ah[4], al[4];
                ah[0] = *(const uint32_t*)(Ah + off);
                ah[1] = *(const uint32_t*)(Ah + off + 8 * ASTR);
                ah[2] = *(const uint32_t*)(Ah + off + 8);
                ah[3] = *(const uint32_t*)(Ah + off + 8 * ASTR + 8);
                al[0] = *(const uint32_t*)(Al + off);
                al[1] = *(const uint32_t*)(Al + off + 8 * ASTR);
                al[2] = *(const uint32_t*)(Al + off + 8);
                al[3] = *(const uint32_t*)(Al + off + 8 * ASTR + 8);
                #pragma unroll
                for (int nt = 0; nt < 4; nt++) {
                    mma16816(acc[mt][nt], ah, bh[nt]);
                    mma16816(acc[mt][nt], ah, bl[nt]);
                    mma16816(acc[mt][nt], al, bh[nt]);
                }
            }
        }
        // no trailing barrier needed: next iteration writes the other stage,
        // and its barrier orders that store against everyone's compute here.
        __syncthreads();
    }

    // epilogue
    #pragma unroll
    for (int mt = 0; mt < 4; mt++) {
        int m = m0 + wm * 64 + mt * 16 + gid;
        #pragma unroll
        for (int nt = 0; nt < 4; nt++) {
            int col = n0 + wn * 32 + nt * 8 + tig * 2;
            float b0 = 0.f, b1 = 0.f;
            if (HASB) { b0 = bias[col]; b1 = bias[col + 1]; }
            float2 v0, v1;
            v0.x = acc[mt][nt][0] + b0; v0.y = acc[mt][nt][1] + b1;
            v1.x = acc[mt][nt][2] + b0; v1.y = acc[mt][nt][3] + b1;
            if (RELU) {
                v0.x = fmaxf(v0.x, 0.f); v0.y = fmaxf(v0.y, 0.f);
                v1.x = fmaxf(v1.x, 0.f); v1.y = fmaxf(v1.y, 0.f);
            }
            *(float2*)&C[(long)m * N + col]       = v0;
            *(float2*)&C[(long)(m + 8) * N + col] = v1;
        }
    }
}

// ===========================================================================
// Weight packing for conv-as-GEMM
// ===========================================================================
__device__ __forceinline__ void decode_kg(int kg, int& K, int& k)
{
    if (kg < 3)      { K = 3; k = kg; }
    else if (kg < 7) { K = 4; k = kg - 3; }
    else             { K = 5; k = kg - 7; }
}

__global__ void pack_wg(const float* __restrict__ c1w3, const float* __restrict__ c1w4,
                        const float* __restrict__ c1w5, const float* __restrict__ c2w3,
                        const float* __restrict__ c2w4, const float* __restrict__ c2w5)
{
    long idx = (long)blockIdx.x * 256 + threadIdx.x;
    if (idx >= (long)NG_PAD * Hh) return;
    int ch = idx / Hh, h = idx % Hh;
    float v = 0.f;
    if (ch < 2400) {
        int kg = ch / 200, r = ch % 200;
        int conv = r / 100, co = r % 100;
        int K, k; decode_kg(kg, K, k);
        const float* w;
        if (conv == 0) w = (K == 3) ? c1w3 : (K == 4) ? c1w4 : c1w5;
        else           w = (K == 3) ? c2w3 : (K == 4) ? c2w4 : c2w5;
        v = w[(long)co * Hh * K + h * K + k];
    }
    g_Wg[idx] = v;
}

__global__ void pack_wa(const float* __restrict__ c3w3, const float* __restrict__ c3w4,
                        const float* __restrict__ c3w5)
{
    long idx = (long)blockIdx.x * 256 + threadIdx.x;
    if (idx >= (long)NA_PAD * Hh) return;
    int ch = idx / Hh, h = idx % Hh;
    float v = 0.f;
    if (ch < 1200) {
        int kg = ch / 100, co = ch % 100;
        int K, k; decode_kg(kg, K, k);
        const float* w = (K == 3) ? c3w3 : (K == 4) ? c3w4 : c3w5;
        v = w[(long)co * Hh * K + h * K + k];
    }
    g_Wa[idx] = v;
}

// ===========================================================================
// Pointwise / epilogue / routing kernels
// ===========================================================================
__global__ void squash_kernel()
{
    int idx = blockIdx.x * 256 + threadIdx.x;
    if (idx >= MSZ) return;
    float v[6];
    v[0] = g_h2[(long)5 * MSZ + idx];
    #pragma unroll
    for (int j = 1; j < 6; j++) v[j] = g_h2[(long)(j - 1) * MSZ + idx];
    float sq = 1e-16f;
    #pragma unroll
    for (int j = 0; j < 6; j++) sq += v[j] * v[j];
    float sc = sqrtf(sq) / (1.f + sq);
    #pragma unroll
    for (int j = 0; j < 6; j++) g_sq[(long)j * MSZ + idx] = v[j] * sc;
}

__global__ void aspect_epi(const float* __restrict__ b3, const float* __restrict__ b4,
                           const float* __restrict__ b5)
{
    int b = blockIdx.x, t = threadIdx.x;
    if (t >= 300) return;
    int g = t / 100, co = t % 100;
    int K = 3 + g;
    int base = (g == 0) ? 0 : (g == 1) ? 3 : 7;
    int pad = K - 2;
    const float* bias = (g == 0) ? b3 : (g == 1) ? b4 : b5;
    float bb = bias[co];
    int Lout = 125 + K;
    float best = 0.f;
    for (int l = 0; l < Lout; l++) {
        float s = bb;
        for (int k = 0; k < K; k++) {
            int ss = l + k - pad;
            if (ss >= 0 && ss < Ss)
                s += g_Ya[((long)b * Ss + ss) * NA_PAD + (base + k) * 100 + co];
        }
        best = fmaxf(best, s);
    }
    g_aspf[b * 300 + t] = best;
}

__global__ void fca_kernel(const float* __restrict__ fw, const float* __restrict__ fb)
{
    __shared__ float af[300];
    int b = blockIdx.x, tid = threadIdx.x;
    for (int i = tid; i < 300; i += 128) af[i] = g_aspf[b * 300 + i];
    __syncthreads();
    if (tid < COn) {
        float s = fb[tid];
        for (int c = 0; c < 300; c++) s += af[c] * fw[tid * 300 + c];
        g_asp[b * COn + tid] = s;
    }
}

__global__ void gated_epi(const float* __restrict__ b13, const float* __restrict__ b14,
                          const float* __restrict__ b15, const float* __restrict__ b23,
                          const float* __restrict__ b24, const float* __restrict__ b25)
{
    int i = blockIdx.x, t = threadIdx.x;
    if (t >= 300) return;
    int b = i & 63;
    int g = t / 100, co = t % 100;
    int K = 3 + g;
    int base = (g == 0) ? 0 : (g == 1) ? 3 : 7;
    const float* bias1 = (g == 0) ? b13 : (g == 1) ? b14 : b15;
    const float* bias2 = (g == 0) ? b23 : (g == 1) ? b24 : b25;
    float c1b = bias1[co];
    float c2b = bias2[co] + g_asp[b * COn + co];
    int Lout = Ss - K + 1;
    float best = -1e30f;
    for (int l = 0; l < Lout; l++) {
        float s1 = c1b, s2 = c2b;
        for (int k = 0; k < K; k++) {
            long row = (long)i * Ss + l + k;
            s1 += g_Yg[row * NG_PAD + (base + k) * 200 + co];
            s2 += g_Yg[row * NG_PAD + (base + k) * 200 + 100 + co];
        }
        float val = tanhf(s1) * fmaxf(s2, 0.f);
        best = fmaxf(best, val);
    }
    g_z[i * 300 + t] = best;
}

__global__ void priors_kernel(const float* __restrict__ rw)
{
    __shared__ float cap[1800];
    int b = blockIdx.x, n = blockIdx.y, tid = threadIdx.x;
    for (int idx = tid; idx < 1800; idx += 72) {
        int i = idx / 300, c = idx % 300;
        cap[idx] = (i == 0) ? g_aspf[b * 300 + c] : g_z[((i - 1) * Bb + b) * 300 + c];
    }
    __syncthreads();
    int i = tid / 12, s = tid % 12;
    float acc = 0.f;
    const float* rp = rw + ((long)(n * 6 + i) * 300) * 12 + s;
    const float* cp = &cap[i * 300];
    for (int c = 0; c < 300; c++) acc += cp[c] * rp[c * 12];
    g_priors[((n * Bb + b) * 6 + i) * 12 + s] = acc;
}

__global__ void routing_kernel()
{
    int gid = blockIdx.x * blockDim.x + threadIdx.x;
    if (gid >= Nn * Bb) return;
    float pr[72];
    #pragma unroll
    for (int j = 0; j < 72; j++) pr[j] = g_priors[gid * 72 + j];

    float logits[6] = {0, 0, 0, 0, 0, 0};
    float vote[12];
    #pragma unroll
    for (int it = 0; it < 3; it++) {
        float mx = logits[0];
        #pragma unroll
        for (int i = 1; i < 6; i++) mx = fmaxf(mx, logits[i]);
        float e[6], se = 0.f;
        #pragma unroll
        for (int i = 0; i < 6; i++) { e[i] = expf(logits[i] - mx); se += e[i]; }
        float inv = 1.f / se;
        #pragma unroll
        for (int s = 0; s < 12; s++) {
            float v = 0.f;
            #pragma unroll
            for (int i = 0; i < 6; i++) v += e[i] * pr[i * 12 + s];
            vote[s] = v * inv;
        }
        if (it < 2) {
            float sq = 1e-16f;
            #pragma unroll
            for (int s = 0; s < 12; s++) sq += vote[s] * vote[s];
            float sc = sqrtf(sq) / (1.f + sq);
            #pragma unroll
            for (int i = 0; i < 6; i++) {
                float d = 0.f;
                #pragma unroll
                for (int s = 0; s < 12; s++) d += pr[i * 12 + s] * vote[s];
                logits[i] += d * sc;
            }
        }
    }
    #pragma unroll
    for (int s = 0; s < 12; s++) g_vote[gid * 12 + s] = vote[s];
}

__global__ void final_kernel(const float* __restrict__ x, float* __restrict__ out)
{
    int idx = blockIdx.x * 256 + threadIdx.x;
    if (idx >= MSZ) return;
    int b = idx / (Ss * Hh);
    int h = idx % Hh;
    out[idx] = x[idx] + g_h2[(long)5 * MSZ + idx] + g_vote[b * Hh + h];
}

// ===========================================================================
extern "C" void kernel_launch(void* const* d_in, const int* in_sizes, int n_in,
                              void* d_out, int out_size)
{
    const float* x     = (const float*)d_in[0];
    const float* fc1_w = (const float*)d_in[1];
    const float* fc1_b = (const float*)d_in[2];
    const float* fc2_w = (const float*)d_in[3];
    const float* fc2_b = (const float*)d_in[4];
    const float* c1_w3 = (const float*)d_in[5];
    const float* c1_b3 = (const float*)d_in[6];
    const float* c1_w4 = (const float*)d_in[7];
    const float* c1_b4 = (const float*)d_in[8];
    const float* c1_w5 = (const float*)d_in[9];
    const float* c1_b5 = (const float*)d_in[10];
    const float* c2_w3 = (const float*)d_in[11];
    const float* c2_b3 = (const float*)d_in[12];
    const float* c2_w4 = (const float*)d_in[13];
    const float* c2_b4 = (const float*)d_in[14];
    const float* c2_w5 = (const float*)d_in[15];
    const float* c2_b5 = (const float*)d_in[16];
    const float* c3_w3 = (const float*)d_in[17];
    const float* c3_b3 = (const float*)d_in[18];
    const float* c3_w4 = (const float*)d_in[19];
    const float* c3_b4 = (const float*)d_in[20];
    const float* c3_w5 = (const float*)d_in[21];
    const float* c3_b5 = (const float*)d_in[22];
    const float* fca_w = (const float*)d_in[23];
    const float* fca_b = (const float*)d_in[24];
    const float* rw    = (const float*)d_in[25];
    float* out = (float*)d_out;

    float *p_h1, *p_h2, *p_sq, *p_Wg, *p_Wa, *p_Yg, *p_Ya;
    cudaGetSymbolAddress((void**)&p_h1, g_h1);
    cudaGetSymbolAddress((void**)&p_h2, g_h2);
    cudaGetSymbolAddress((void**)&p_sq, g_sq);
    cudaGetSymbolAddress((void**)&p_Wg, g_Wg);
    cudaGetSymbolAddress((void**)&p_Wa, g_Wa);
    cudaGetSymbolAddress((void**)&p_Yg, g_Yg);
    cudaGetSymbolAddress((void**)&p_Ya, g_Ya);

    cudaFuncSetAttribute(mma_gemm<true, true>,
                         cudaFuncAttributeMaxDynamicSharedMemorySize, SMEM_REQ);
    cudaFuncSetAttribute(mma_gemm<false, false>,
                         cudaFuncAttributeMaxDynamicSharedMemorySize, SMEM_REQ);

    // 0) pack conv weights
    pack_wg<<<((long)NG_PAD * Hh + 255) / 256, 256>>>(c1_w3, c1_w4, c1_w5, c2_w3, c2_w4, c2_w5);
    pack_wa<<<((long)NA_PAD * Hh + 255) / 256, 256>>>(c3_w3, c3_w4, c3_w5);

    // 1) h1 = relu(x @ fc1_w^T + fc1_b)
    mma_gemm<true, true><<<dim3(Aa / 128, M1 / 128, T1K), 256, SMEM_REQ>>>(
        x, fc1_w, fc1_b, p_h1, Aa, Hh,
        0L, (long)Aa * Hh, (long)Aa, (long)M1 * Aa);

    // 2) h2 = relu(h1 @ fc2_w^T + fc2_b)
    mma_gemm<true, true><<<dim3(Hh / 128, M1 / 128, T1K), 256, SMEM_REQ>>>(
        p_h1, fc2_w, fc2_b, p_h2, Hh, Aa,
        (long)M1 * Aa, (long)Hh * Aa, (long)Hh, (long)M1 * Hh);

    // 3) squash
    squash_kernel<<<(MSZ + 255) / 256, 256>>>();

    // 4) conv GEMMs
    mma_gemm<false, false><<<dim3(NA_PAD / 128, M1 / 128, 1), 256, SMEM_REQ>>>(
        p_sq, p_Wa, nullptr, p_Ya, NA_PAD, Hh, 0L, 0L, 0L, 0L);
    mma_gemm<false, false><<<dim3(NG_PAD / 128, MG / 128, 1), 256, SMEM_REQ>>>(
        p_sq + (long)MSZ, p_Wg, nullptr, p_Yg, NG_PAD, Hh, 0L, 0L, 0L, 0L);

    // 5) epilogues
    aspect_epi<<<Bb, 320>>>(c3_b3, c3_b4, c3_b5);
    fca_kernel<<<Bb, 128>>>(fca_w, fca_b);
    gated_epi<<<TnK * Bb, 320>>>(c1_b3, c1_b4, c1_b5, c2_b3, c2_b4, c2_b5);

    // 6) priors + routing
    priors_kernel<<<dim3(Bb, Nn), 72>>>(rw);
    routing_kernel<<<16, 256>>>();

    // 7) residual add
    final_kernel<<<(MSZ + 255) / 256, 256>>>(x, out);
}

// round 5
// speedup vs baseline: 26.0164x; 1.0649x over previous
#include <cuda_runtime.h>
#include <cuda_bf16.h>
#include <math.h>
#include <stdint.h>

// Problem constants
#define Bb   64
#define Ss   128
#define Hh   768
#define Aa   512
#define COn  100
#define TnK  5
#define T1K  6
#define Nn   64
#define SCn  12
#define MSZ  (Bb*Ss*Hh)      // 6291456
#define M1   (Bb*Ss)         // 8192

#define NG_PAD 2432
#define NA_PAD 1280
#define MG     (TnK*M1)      // 40960

// ---------------------------------------------------------------------------
// Scratch (static device globals — allocation-free)
// ---------------------------------------------------------------------------
__device__ __nv_bfloat16 g_xh[MSZ],  g_xl[MSZ];
__device__ __nv_bfloat16 g_f1h[T1K * Aa * Hh], g_f1l[T1K * Aa * Hh];
__device__ __nv_bfloat16 g_f2h[T1K * Hh * Aa], g_f2l[T1K * Hh * Aa];
__device__ __nv_bfloat16 g_h1h[T1K * M1 * Aa], g_h1l[T1K * M1 * Aa];
__device__ float         g_h2[T1K * MSZ];
__device__ __nv_bfloat16 g_sqh[T1K * MSZ], g_sql[T1K * MSZ];
__device__ __nv_bfloat16 g_Wgh[NG_PAD * Hh], g_Wgl[NG_PAD * Hh];
__device__ __nv_bfloat16 g_Wah[NA_PAD * Hh], g_Wal[NA_PAD * Hh];
__device__ float g_Yg[(long)MG * NG_PAD];
__device__ float g_Ya[(long)M1 * NA_PAD];
__device__ float g_aspf[Bb * 3 * COn];
__device__ float g_asp[Bb * COn];
__device__ float g_z[TnK * Bb * 3 * COn];
__device__ float g_priors[Nn * Bb * T1K * SCn];
__device__ float g_vote[Nn * Bb * SCn];

// ---------------------------------------------------------------------------
// helpers
// ---------------------------------------------------------------------------
__device__ __forceinline__ void mma16816(float* c, const uint32_t* a, const uint32_t* b)
{
    asm volatile(
        "mma.sync.aligned.m16n8k16.row.col.f32.bf16.bf16.f32 "
        "{%0,%1,%2,%3}, {%4,%5,%6,%7}, {%8,%9}, {%0,%1,%2,%3};"
        : "+f"(c[0]), "+f"(c[1]), "+f"(c[2]), "+f"(c[3])
        : "r"(a[0]), "r"(a[1]), "r"(a[2]), "r"(a[3]), "r"(b[0]), "r"(b[1]));
}

// pack two floats -> bf16x2 hi + bf16x2 lo (Dekker)
__device__ __forceinline__ void split2(float x0, float x1, uint32_t& hp, uint32_t& lp)
{
    asm("cvt.rn.bf16x2.f32 %0, %1, %2;" : "=r"(hp) : "f"(x1), "f"(x0));
    float h0 = __uint_as_float(hp << 16);
    float h1 = __uint_as_float(hp & 0xffff0000u);
    float r0 = x0 - h0, r1 = x1 - h1;
    asm("cvt.rn.bf16x2.f32 %0, %1, %2;" : "=r"(lp) : "f"(r1), "f"(r0));
}

__device__ __forceinline__ void cp16(void* sdst, const void* gsrc)
{
    uint32_t s = (uint32_t)__cvta_generic_to_shared(sdst);
    asm volatile("cp.async.cg.shared.global [%0], [%1], 16;" :: "r"(s), "l"(gsrc));
}
#define CP_COMMIT() asm volatile("cp.async.commit_group;" ::: "memory")
#define CP_WAIT0()  asm volatile("cp.async.wait_group 0;" ::: "memory")

// ===========================================================================
// Warp-MMA GEMM with pre-split bf16 operands + cp.async pipeline
// C[m,n] = post( sum_k A[m,k]*W[n,k] + bias[n] )
// OUT: 0 = fp32 plain, 1 = fp32 bias+relu, 2 = bf16 hi/lo bias+relu
// ===========================================================================
#define KC       32
#define RSTR     40                     // bf16 elems per smem row
#define MAT_ELE  (128 * RSTR)           // 5120
#define STG_ELE  (4 * MAT_ELE)          // Ah, Al, Bh, Bl
#define SMEM_REQ (2 * STG_ELE * 2)      // 81920 bytes

template<int OUT>
__global__ void __launch_bounds__(256, 2)
mma_gemm(const __nv_bfloat16* __restrict__ Ah, const __nv_bfloat16* __restrict__ Al,
         const __nv_bfloat16* __restrict__ Bh, const __nv_bfloat16* __restrict__ Bl,
         const float* __restrict__ bias,
         float* __restrict__ Cf, __nv_bfloat16* __restrict__ Chi, __nv_bfloat16* __restrict__ Clo,
         int N, int Kd, long sA, long sW, long sB, long sC)
{
    extern __shared__ __nv_bfloat16 sm[];
    long zo = blockIdx.z * sA;
    Ah += zo; Al += zo;
    zo = blockIdx.z * sW;
    Bh += zo; Bl += zo;
    if (OUT) bias += blockIdx.z * sB;
    long co = blockIdx.z * sC;

    int m0 = blockIdx.y * 128, n0 = blockIdx.x * 128;
    int tid = threadIdx.x, lane = tid & 31, wid = tid >> 5;
    int wm = wid >> 2, wn = wid & 3;
    int gid = lane >> 2, tig = lane & 3;

    int crow = tid >> 2, cch = (tid & 3) * 8;   // copy coords

    auto issue = [&](int c, int st) {
        __nv_bfloat16* base = sm + st * STG_ELE;
        int k0 = c * KC;
        #pragma unroll
        for (int r = 0; r < 2; r++) {
            int row = crow + r * 64;
            long ga = (long)(m0 + row) * Kd + k0 + cch;
            long gb = (long)(n0 + row) * Kd + k0 + cch;
            int so = row * RSTR + cch;
            cp16(base + so,               Ah + ga);
            cp16(base + MAT_ELE + so,     Al + ga);
            cp16(base + 2 * MAT_ELE + so, Bh + gb);
            cp16(base + 3 * MAT_ELE + so, Bl + gb);
        }
        CP_COMMIT();
    };

    float acc[4][4][4] = {};
    int nch = Kd / KC;

    issue(0, 0);

    for (int c = 0; c < nch; c++) {
        CP_WAIT0();
        __syncthreads();
        if (c + 1 < nch) issue(c + 1, (c + 1) & 1);

        const __nv_bfloat16* Ahs = sm + (c & 1) * STG_ELE;
        const __nv_bfloat16* Als = Ahs + MAT_ELE;
        const __nv_bfloat16* Bhs = Als + MAT_ELE;
        const __nv_bfloat16* Bls = Bhs + MAT_ELE;

        #pragma unroll
        for (int kk = 0; kk < KC; kk += 16) {
            uint32_t bh[4][2], bl[4][2];
            #pragma unroll
            for (int nt = 0; nt < 4; nt++) {
                int off = (wn * 32 + nt * 8 + gid) * RSTR + kk + tig * 2;
                bh[nt][0] = *(const uint32_t*)(Bhs + off);
                bh[nt][1] = *(const uint32_t*)(Bhs + off + 8);
                bl[nt][0] = *(const uint32_t*)(Bls + off);
                bl[nt][1] = *(const uint32_t*)(Bls + off + 8);
            }
            #pragma unroll
            for (int mt = 0; mt < 4; mt++) {
                int off = (wm * 64 + mt * 16 + gid) * RSTR + kk + tig * 2;
                uint32_t ah[4], al[4];
                ah[0] = *(const uint32_t*)(Ahs + off);
                ah[1] = *(const uint32_t*)(Ahs + off + 8 * RSTR);
                ah[2] = *(const uint32_t*)(Ahs + off + 8);
                ah[3] = *(const uint32_t*)(Ahs + off + 8 * RSTR + 8);
                al[0] = *(const uint32_t*)(Als + off);
                al[1] = *(const uint32_t*)(Als + off + 8 * RSTR);
                al[2] = *(const uint32_t*)(Als + off + 8);
                al[3] = *(const uint32_t*)(Als + off + 8 * RSTR + 8);
                #pragma unroll
                for (int nt = 0; nt < 4; nt++) {
                    mma16816(acc[mt][nt], ah, bh[nt]);
                    mma16816(acc[mt][nt], ah, bl[nt]);
                    mma16816(acc[mt][nt], al, bh[nt]);
                }
            }
        }
        __syncthreads();
    }

    // epilogue
    #pragma unroll
    for (int mt = 0; mt < 4; mt++) {
        long m = m0 + wm * 64 + mt * 16 + gid;
        #pragma unroll
        for (int nt = 0; nt < 4; nt++) {
            int col = n0 + wn * 32 + nt * 8 + tig * 2;
            float b0 = 0.f, b1 = 0.f;
            if (OUT) { b0 = bias[col]; b1 = bias[col + 1]; }
            float v00 = acc[mt][nt][0] + b0, v01 = acc[mt][nt][1] + b1;
            float v10 = acc[mt][nt][2] + b0, v11 = acc[mt][nt][3] + b1;
            if (OUT) {
                v00 = fmaxf(v00, 0.f); v01 = fmaxf(v01, 0.f);
                v10 = fmaxf(v10, 0.f); v11 = fmaxf(v11, 0.f);
            }
            if (OUT == 2) {
                uint32_t hp, lp;
                split2(v00, v01, hp, lp);
                *(uint32_t*)(Chi + co + m * N + col) = hp;
                *(uint32_t*)(Clo + co + m * N + col) = lp;
                split2(v10, v11, hp, lp);
                *(uint32_t*)(Chi + co + (m + 8) * N + col) = hp;
                *(uint32_t*)(Clo + co + (m + 8) * N + col) = lp;
            } else {
                *(float2*)(Cf + co + m * N + col)       = make_float2(v00, v01);
                *(float2*)(Cf + co + (m + 8) * N + col) = make_float2(v10, v11);
            }
        }
    }
}

// ===========================================================================
// Operand preparation
// ===========================================================================
__global__ void split_arr(const float* __restrict__ in,
                          __nv_bfloat16* __restrict__ hi, __nv_bfloat16* __restrict__ lo,
                          long n)
{
    long i = ((long)blockIdx.x * 256 + threadIdx.x) * 2;
    if (i >= n) return;
    float2 v = *(const float2*)(in + i);
    uint32_t hp, lp;
    split2(v.x, v.y, hp, lp);
    *(uint32_t*)(hi + i) = hp;
    *(uint32_t*)(lo + i) = lp;
}

__device__ __forceinline__ void decode_kg(int kg, int& K, int& k)
{
    if (kg < 3)      { K = 3; k = kg; }
    else if (kg < 7) { K = 4; k = kg - 3; }
    else             { K = 5; k = kg - 7; }
}

__global__ void pack_wg(const float* __restrict__ c1w3, const float* __restrict__ c1w4,
                        const float* __restrict__ c1w5, const float* __restrict__ c2w3,
                        const float* __restrict__ c2w4, const float* __restrict__ c2w5)
{
    long idx = (long)blockIdx.x * 256 + threadIdx.x;
    if (idx >= (long)NG_PAD * Hh) return;
    int ch = idx / Hh, h = idx % Hh;
    float v = 0.f;
    if (ch < 2400) {
        int kg = ch / 200, r = ch % 200;
        int conv = r / 100, cco = r % 100;
        int K, k; decode_kg(kg, K, k);
        const float* w;
        if (conv == 0) w = (K == 3) ? c1w3 : (K == 4) ? c1w4 : c1w5;
        else           w = (K == 3) ? c2w3 : (K == 4) ? c2w4 : c2w5;
        v = w[(long)cco * Hh * K + h * K + k];
    }
    __nv_bfloat16 hb = __float2bfloat16(v);
    g_Wgh[idx] = hb;
    g_Wgl[idx] = __float2bfloat16(v - __bfloat162float(hb));
}

__global__ void pack_wa(const float* __restrict__ c3w3, const float* __restrict__ c3w4,
                        const float* __restrict__ c3w5)
{
    long idx = (long)blockIdx.x * 256 + threadIdx.x;
    if (idx >= (long)NA_PAD * Hh) return;
    int ch = idx / Hh, h = idx % Hh;
    float v = 0.f;
    if (ch < 1200) {
        int kg = ch / 100, cco = ch % 100;
        int K, k; decode_kg(kg, K, k);
        const float* w = (K == 3) ? c3w3 : (K == 4) ? c3w4 : c3w5;
        v = w[(long)cco * Hh * K + h * K + k];
    }
    __nv_bfloat16 hb = __float2bfloat16(v);
    g_Wah[idx] = hb;
    g_Wal[idx] = __float2bfloat16(v - __bfloat162float(hb));
}

// ===========================================================================
// squash: fp32 h2 -> bf16 hi/lo squashed capsules
// ===========================================================================
__global__ void squash_kernel()
{
    int idx = blockIdx.x * 256 + threadIdx.x;
    if (idx >= MSZ) return;
    float v[6];
    v[0] = g_h2[(long)5 * MSZ + idx];
    #pragma unroll
    for (int j = 1; j < 6; j++) v[j] = g_h2[(long)(j - 1) * MSZ + idx];
    float sq = 1e-16f;
    #pragma unroll
    for (int j = 0; j < 6; j++) sq += v[j] * v[j];
    float sc = sqrtf(sq) / (1.f + sq);
    #pragma unroll
    for (int j = 0; j < 6; j++) {
        float s = v[j] * sc;
        __nv_bfloat16 hb = __float2bfloat16(s);
        g_sqh[(long)j * MSZ + idx] = hb;
        g_sql[(long)j * MSZ + idx] = __float2bfloat16(s - __bfloat162float(hb));
    }
}

// ===========================================================================
// Conv epilogues / fca / priors / routing / final (as R4)
// ===========================================================================
__global__ void aspect_epi(const float* __restrict__ b3, const float* __restrict__ b4,
                           const float* __restrict__ b5)
{
    int b = blockIdx.x, t = threadIdx.x;
    if (t >= 300) return;
    int g = t / 100, co = t % 100;
    int K = 3 + g;
    int base = (g == 0) ? 0 : (g == 1) ? 3 : 7;
    int pad = K - 2;
    const float* bias = (g == 0) ? b3 : (g == 1) ? b4 : b5;
    float bb = bias[co];
    int Lout = 125 + K;
    float best = 0.f;
    for (int l = 0; l < Lout; l++) {
        float s = bb;
        for (int k = 0; k < K; k++) {
            int ss = l + k - pad;
            if (ss >= 0 && ss < Ss)
                s += g_Ya[((long)b * Ss + ss) * NA_PAD + (base + k) * 100 + co];
        }
        best = fmaxf(best, s);
    }
    g_aspf[b * 300 + t] = best;
}

__global__ void fca_kernel(const float* __restrict__ fw, const float* __restrict__ fb)
{
    __shared__ float af[300];
    int b = blockIdx.x, tid = threadIdx.x;
    for (int i = tid; i < 300; i += 128) af[i] = g_aspf[b * 300 + i];
    __syncthreads();
    if (tid < COn) {
        float s = fb[tid];
        for (int c = 0; c < 300; c++) s += af[c] * fw[tid * 300 + c];
        g_asp[b * COn + tid] = s;
    }
}

__global__ void gated_epi(const float* __restrict__ b13, const float* __restrict__ b14,
                          const float* __restrict__ b15, const float* __restrict__ b23,
                          const float* __restrict__ b24, const float* __restrict__ b25)
{
    int i = blockIdx.x, t = threadIdx.x;
    if (t >= 300) return;
    int b = i & 63;
    int g = t / 100, co = t % 100;
    int K = 3 + g;
    int base = (g == 0) ? 0 : (g == 1) ? 3 : 7;
    const float* bias1 = (g == 0) ? b13 : (g == 1) ? b14 : b15;
    const float* bias2 = (g == 0) ? b23 : (g == 1) ? b24 : b25;
    float c1b = bias1[co];
    float c2b = bias2[co] + g_asp[b * COn + co];
    int Lout = Ss - K + 1;
    float best = -1e30f;
    for (int l = 0; l < Lout; l++) {
        float s1 = c1b, s2 = c2b;
        for (int k = 0; k < K; k++) {
            long row = (long)i * Ss + l + k;
            s1 += g_Yg[row * NG_PAD + (base + k) * 200 + co];
            s2 += g_Yg[row * NG_PAD + (base + k) * 200 + 100 + co];
        }
        float val = tanhf(s1) * fmaxf(s2, 0.f);
        best = fmaxf(best, val);
    }
    g_z[i * 300 + t] = best;
}

__global__ void priors_kernel(const float* __restrict__ rw)
{
    __shared__ float cap[1800];
    int b = blockIdx.x, n = blockIdx.y, tid = threadIdx.x;
    for (int idx = tid; idx < 1800; idx += 72) {
        int i = idx / 300, c = idx % 300;
        cap[idx] = (i == 0) ? g_aspf[b * 300 + c] : g_z[((i - 1) * Bb + b) * 300 + c];
    }
    __syncthreads();
    int i = tid / 12, s = tid % 12;
    float acc = 0.f;
    const float* rp = rw + ((long)(n * 6 + i) * 300) * 12 + s;
    const float* cp = &cap[i * 300];
    for (int c = 0; c < 300; c++) acc += cp[c] * rp[c * 12];
    g_priors[((n * Bb + b) * 6 + i) * 12 + s] = acc;
}

__global__ void routing_kernel()
{
    int gid = blockIdx.x * blockDim.x + threadIdx.x;
    if (gid >= Nn * Bb) return;
    float pr[72];
    #pragma unroll
    for (int j = 0; j < 72; j++) pr[j] = g_priors[gid * 72 + j];

    float logits[6] = {0, 0, 0, 0, 0, 0};
    float vote[12];
    #pragma unroll
    for (int it = 0; it < 3; it++) {
        float mx = logits[0];
        #pragma unroll
        for (int i = 1; i < 6; i++) mx = fmaxf(mx, logits[i]);
        float e[6], se = 0.f;
        #pragma unroll
        for (int i = 0; i < 6; i++) { e[i] = expf(logits[i] - mx); se += e[i]; }
        float inv = 1.f / se;
        #pragma unroll
        for (int s = 0; s < 12; s++) {
            float v = 0.f;
            #pragma unroll
            for (int i = 0; i < 6; i++) v += e[i] * pr[i * 12 + s];
            vote[s] = v * inv;
        }
        if (it < 2) {
            float sq = 1e-16f;
            #pragma unroll
            for (int s = 0; s < 12; s++) sq += vote[s] * vote[s];
            float sc = sqrtf(sq) / (1.f + sq);
            #pragma unroll
            for (int i = 0; i < 6; i++) {
                float d = 0.f;
                #pragma unroll
                for (int s = 0; s < 12; s++) d += pr[i * 12 + s] * vote[s];
                logits[i] += d * sc;
            }
        }
    }
    #pragma unroll
    for (int s = 0; s < 12; s++) g_vote[gid * 12 + s] = vote[s];
}

__global__ void final_kernel(const float* __restrict__ x, float* __restrict__ out)
{
    int idx = blockIdx.x * 256 + threadIdx.x;
    if (idx >= MSZ) return;
    int b = idx / (Ss * Hh);
    int h = idx % Hh;
    out[idx] = x[idx] + g_h2[(long)5 * MSZ + idx] + g_vote[b * Hh + h];
}

// ===========================================================================
extern "C" void kernel_launch(void* const* d_in, const int* in_sizes, int n_in,
                              void* d_out, int out_size)
{
    const float* x     = (const float*)d_in[0];
    const float* fc1_w = (const float*)d_in[1];
    const float* fc1_b = (const float*)d_in[2];
    const float* fc2_w = (const float*)d_in[3];
    const float* fc2_b = (const float*)d_in[4];
    const float* c1_w3 = (const float*)d_in[5];
    const float* c1_b3 = (const float*)d_in[6];
    const float* c1_w4 = (const float*)d_in[7];
    const float* c1_b4 = (const float*)d_in[8];
    const float* c1_w5 = (const float*)d_in[9];
    const float* c1_b5 = (const float*)d_in[10];
    const float* c2_w3 = (const float*)d_in[11];
    const float* c2_b3 = (const float*)d_in[12];
    const float* c2_w4 = (const float*)d_in[13];
    const float* c2_b4 = (const float*)d_in[14];
    const float* c2_w5 = (const float*)d_in[15];
    const float* c2_b5 = (const float*)d_in[16];
    const float* c3_w3 = (const float*)d_in[17];
    const float* c3_b3 = (const float*)d_in[18];
    const float* c3_w4 = (const float*)d_in[19];
    const float* c3_b4 = (const float*)d_in[20];
    const float* c3_w5 = (const float*)d_in[21];
    const float* c3_b5 = (const float*)d_in[22];
    const float* fca_w = (const float*)d_in[23];
    const float* fca_b = (const float*)d_in[24];
    const float* rw    = (const float*)d_in[25];
    float* out = (float*)d_out;

    __nv_bfloat16 *p_xh, *p_xl, *p_f1h, *p_f1l, *p_f2h, *p_f2l;
    __nv_bfloat16 *p_h1h, *p_h1l, *p_sqh, *p_sql, *p_Wgh, *p_Wgl, *p_Wah, *p_Wal;
    float *p_h2, *p_Yg, *p_Ya;
    cudaGetSymbolAddress((void**)&p_xh,  g_xh);
    cudaGetSymbolAddress((void**)&p_xl,  g_xl);
    cudaGetSymbolAddress((void**)&p_f1h, g_f1h);
    cudaGetSymbolAddress((void**)&p_f1l, g_f1l);
    cudaGetSymbolAddress((void**)&p_f2h, g_f2h);
    cudaGetSymbolAddress((void**)&p_f2l, g_f2l);
    cudaGetSymbolAddress((void**)&p_h1h, g_h1h);
    cudaGetSymbolAddress((void**)&p_h1l, g_h1l);
    cudaGetSymbolAddress((void**)&p_sqh, g_sqh);
    cudaGetSymbolAddress((void**)&p_sql, g_sql);
    cudaGetSymbolAddress((void**)&p_Wgh, g_Wgh);
    cudaGetSymbolAddress((void**)&p_Wgl, g_Wgl);
    cudaGetSymbolAddress((void**)&p_Wah, g_Wah);
    cudaGetSymbolAddress((void**)&p_Wal, g_Wal);
    cudaGetSymbolAddress((void**)&p_h2,  g_h2);
    cudaGetSymbolAddress((void**)&p_Yg,  g_Yg);
    cudaGetSymbolAddress((void**)&p_Ya,  g_Ya);

    cudaFuncSetAttribute(mma_gemm<0>, cudaFuncAttributeMaxDynamicSharedMemorySize, SMEM_REQ);
    cudaFuncSetAttribute(mma_gemm<1>, cudaFuncAttributeMaxDynamicSharedMemorySize, SMEM_REQ);
    cudaFuncSetAttribute(mma_gemm<2>, cudaFuncAttributeMaxDynamicSharedMemorySize, SMEM_REQ);

    // 0) operand prep
    split_arr<<<(MSZ / 2 + 255) / 256, 256>>>(x, p_xh, p_xl, MSZ);
    split_arr<<<((long)T1K * Aa * Hh / 2 + 255) / 256, 256>>>(fc1_w, p_f1h, p_f1l, (long)T1K * Aa * Hh);
    split_arr<<<((long)T1K * Hh * Aa / 2 + 255) / 256, 256>>>(fc2_w, p_f2h, p_f2l, (long)T1K * Hh * Aa);
    pack_wg<<<((long)NG_PAD * Hh + 255) / 256, 256>>>(c1_w3, c1_w4, c1_w5, c2_w3, c2_w4, c2_w5);
    pack_wa<<<((long)NA_PAD * Hh + 255) / 256, 256>>>(c3_w3, c3_w4, c3_w5);

    // 1) h1 = relu(x @ fc1_w^T + b)  -> bf16 hi/lo
    mma_gemm<2><<<dim3(Aa / 128, M1 / 128, T1K), 256, SMEM_REQ>>>(
        p_xh, p_xl, p_f1h, p_f1l, fc1_b, nullptr, p_h1h, p_h1l,
        Aa, Hh, 0L, (long)Aa * Hh, (long)Aa, (long)M1 * Aa);

    // 2) h2 = relu(h1 @ fc2_w^T + b) -> fp32
    mma_gemm<1><<<dim3(Hh / 128, M1 / 128, T1K), 256, SMEM_REQ>>>(
        p_h1h, p_h1l, p_f2h, p_f2l, fc2_b, p_h2, nullptr, nullptr,
        Hh, Aa, (long)M1 * Aa, (long)Hh * Aa, (long)Hh, (long)M1 * Hh);

    // 3) squash -> bf16 hi/lo capsules
    squash_kernel<<<(MSZ + 255) / 256, 256>>>();

    // 4) conv GEMMs
    mma_gemm<0><<<dim3(NA_PAD / 128, M1 / 128, 1), 256, SMEM_REQ>>>(
        p_sqh, p_sql, p_Wah, p_Wal, nullptr, p_Ya, nullptr, nullptr,
        NA_PAD, Hh, 0L, 0L, 0L, 0L);
    mma_gemm<0><<<dim3(NG_PAD / 128, MG / 128, 1), 256, SMEM_REQ>>>(
        p_sqh + (long)MSZ, p_sql + (long)MSZ, p_Wgh, p_Wgl, nullptr, p_Yg, nullptr, nullptr,
        NG_PAD, Hh, 0L, 0L, 0L, 0L);

    // 5) epilogues
    aspect_epi<<<Bb, 320>>>(c3_b3, c3_b4, c3_b5);
    fca_kernel<<<Bb, 128>>>(fca_w, fca_b);
    gated_epi<<<TnK * Bb, 320>>>(c1_b3, c1_b4, c1_b5, c2_b3, c2_b4, c2_b5);

    // 6) priors + routing
    priors_kernel<<<dim3(Bb, Nn), 72>>>(rw);
    routing_kernel<<<16, 256>>>();

    // 7) residual add
    final_kernel<<<(MSZ + 255) / 256, 256>>>(x, out);
}